// round 10
// baseline (speedup 1.0000x reference)
#include <cuda_runtime.h>
#include <math.h>

#define B_  32
#define T_  2048
#define D_  512
#define H_  512
#define G4_ 2048   // 4*H

// ---------------- device scratch ----------------
__device__ float g_xp[(size_t)B_ * T_ * G4_];   // x_proj scratch [B][T][4H]
__device__ float g_h[2][B_ * H_];               // double-buffered hidden state
__device__ unsigned int g_ctr4[4 * 64];         // per-bgrp counters, 256B apart

typedef unsigned long long ull;

// ---------------- packed f32x2 helpers ----------------
__device__ __forceinline__ ull pk(float lo, float hi) {
    ull r;
    asm("mov.b64 %0, {%1, %2};" : "=l"(r) : "f"(lo), "f"(hi));
    return r;
}
__device__ __forceinline__ ull fma2(ull a, ull b, ull c) {
    ull d;
    asm("fma.rn.f32x2 %0, %1, %2, %3;" : "=l"(d) : "l"(a), "l"(b), "l"(c));
    return d;
}

// ---------------- barrier primitives (v6 style: non-returning red) -----
__device__ __forceinline__ void red_add_release(unsigned int* p, unsigned int v) {
    asm volatile("red.release.gpu.add.u32 [%0], %1;" :: "l"(p), "r"(v) : "memory");
}
__device__ __forceinline__ unsigned int ld_acquire(unsigned int* p) {
    unsigned int v;
    asm volatile("ld.acquire.gpu.u32 %0, [%1];" : "=r"(v) : "l"(p) : "memory");
    return v;
}

// =====================================================================
// Phase 1: x_proj = inputs @ Wi  (v6 single-buffered version, ~3.0 ms)
// =====================================================================
#define BM 128
#define BN 128
#define BKK 8

__global__ __launch_bounds__(256) void gemm_xproj(const float* __restrict__ A,
                                                  const float* __restrict__ Bw) {
    __shared__ float As[BKK][BM + 4];
    __shared__ float Bs[BKK][BN + 4];

    const int tid = threadIdx.x;
    const int m0 = blockIdx.y * BM;
    const int n0 = blockIdx.x * BN;
    const int tx = tid & 15;
    const int ty = tid >> 4;

    const int arow = tid >> 1;
    const int akq  = (tid & 1) * 4;
    const int bkr  = tid >> 5;
    const int bq   = tid & 31;

    ull acc[8][4];
#pragma unroll
    for (int i = 0; i < 8; i++)
#pragma unroll
        for (int j = 0; j < 4; j++) acc[i][j] = 0ull;

    for (int kt = 0; kt < D_ / BKK; ++kt) {
        float4 av = *(const float4*)&A[(size_t)(m0 + arow) * D_ + kt * BKK + akq];
        As[akq + 0][arow] = av.x;
        As[akq + 1][arow] = av.y;
        As[akq + 2][arow] = av.z;
        As[akq + 3][arow] = av.w;
        float4 bv = *(const float4*)&Bw[(size_t)(kt * BKK + bkr) * G4_ + n0 + bq * 4];
        *(float4*)&Bs[bkr][bq * 4] = bv;
        __syncthreads();

#pragma unroll
        for (int k = 0; k < BKK; ++k) {
            float4 a0 = *(const float4*)&As[k][ty * 8];
            float4 a1 = *(const float4*)&As[k][ty * 8 + 4];
            const ull* bp = (const ull*)&Bs[k][tx * 8];
            ull b0 = bp[0], b1 = bp[1], b2 = bp[2], b3 = bp[3];
            float ar[8] = {a0.x, a0.y, a0.z, a0.w, a1.x, a1.y, a1.z, a1.w};
#pragma unroll
            for (int i = 0; i < 8; i++) {
                ull a2 = pk(ar[i], ar[i]);
                acc[i][0] = fma2(a2, b0, acc[i][0]);
                acc[i][1] = fma2(a2, b1, acc[i][1]);
                acc[i][2] = fma2(a2, b2, acc[i][2]);
                acc[i][3] = fma2(a2, b3, acc[i][3]);
            }
        }
        __syncthreads();
    }

#pragma unroll
    for (int i = 0; i < 8; i++) {
        size_t row = (size_t)(m0 + ty * 8 + i);
#pragma unroll
        for (int j = 0; j < 4; j++) {
            *(float2*)&g_xp[row * G4_ + n0 + tx * 8 + 2 * j] = *(float2*)&acc[i][j];
        }
    }
}

// =====================================================================
// Init
// =====================================================================
__global__ void init_kernel(const float* __restrict__ h0) {
    int i = blockIdx.x * blockDim.x + threadIdx.x;
    if (i < 4 * 64) g_ctr4[i] = 0u;
    if (i < B_ * H_) g_h[0][i] = h0[i];
}

// =====================================================================
// Phase 2 (v9 = v6 + per-bgrp red-barrier + merged reduce/gates)
// 128 blocks = 4 bgrp x 32 cg; block: 8 batches x 16 h-cols.
// 256 threads = 8 k-octants x 32 zc-pairs; thread: 2 z-cols x 64 k in regs.
// =====================================================================
#define HST 516
#define PST 68

__device__ __forceinline__ float sigf(float x) {
    return __fdividef(1.0f, 1.0f + __expf(-x));
}
__device__ __forceinline__ float tanhf_fast(float x) {
    return __fdividef(2.0f, 1.0f + __expf(-2.0f * x)) - 1.0f;
}

__global__ __launch_bounds__(256, 1) void lstm_seq(const float* __restrict__ c0,
                                                   const float* __restrict__ bias,
                                                   const float* __restrict__ Wh,
                                                   float* __restrict__ out) {
    __shared__ __align__(16) float h_s[8 * HST];
    __shared__ __align__(16) float part[64 * PST];
    __shared__ float c_s[8 * 16];
    __shared__ float b_s[64];

    const int tid = threadIdx.x;
    const int bl  = blockIdx.x;

    const int cg   = bl & 31;
    const int bgrp = bl >> 5;
    const int col0 = cg * 16;
    const int gb0  = bgrp * 8;

    unsigned int* ctr = &g_ctr4[bgrp * 64];   // 256B apart -> distinct LTS slices

    // ---- compute mapping: tid = ko*32 + zcp ----
    const int zcp = tid & 31;
    const int ko  = tid >> 5;
    const int k0  = ko * 64;
    const int zct = 2 * zcp;

    // ---- gate mapping (tid < 128): b, j ----
    const int gtb = tid >> 4;        // local batch 0..7
    const int gtj = tid & 15;        // h-col 0..15

    // ---- one-time: Wh slice -> registers (2 cols x 64 k) ----
    ull wreg[2][32];
    {
        const int gcolA = (zct >> 4) * H_ + col0 + (zct & 15);
        const int gcolB = ((zct + 1) >> 4) * H_ + col0 + ((zct + 1) & 15);
#pragma unroll
        for (int kk = 0; kk < 64; kk += 2) {
            wreg[0][kk >> 1] = pk(Wh[(size_t)(k0 + kk) * G4_ + gcolA],
                                  Wh[(size_t)(k0 + kk + 1) * G4_ + gcolA]);
            wreg[1][kk >> 1] = pk(Wh[(size_t)(k0 + kk) * G4_ + gcolB],
                                  Wh[(size_t)(k0 + kk + 1) * G4_ + gcolB]);
        }
    }
    if (tid < 64) b_s[tid] = bias[(tid >> 4) * H_ + col0 + (tid & 15)];
    if (tid < 128) c_s[gtb * 16 + gtj] = c0[(gb0 + gtb) * H_ + col0 + gtj];
    __syncthreads();

    // gate-thread constants
    float bsg0 = 0.f, bsg1 = 0.f, bsg2 = 0.f, bsg3 = 0.f;
    const float* xp_gt = 0;
    if (tid < 128) {
        bsg0 = b_s[gtj];
        bsg1 = b_s[16 + gtj];
        bsg2 = b_s[32 + gtj];
        bsg3 = b_s[48 + gtj];
        xp_gt = g_xp + (size_t)(gb0 + gtb) * T_ * G4_ + col0 + gtj;
    }

    int par = 0;
    for (int t = 0; t < T_; ++t) {
        // ---- stage h slice: 1024 float4, 4 per thread (v6 indexing) ----
        const float* hsrc = g_h[par] + gb0 * H_;
        float4 hreg[4];
#pragma unroll
        for (int i = 0; i < 4; ++i)
            hreg[i] = __ldcg((const float4*)hsrc + tid + i * 256);

        // gate threads prefetch xp for this step (consumed ~2000 cyc later)
        float xq0 = 0.f, xq1 = 0.f, xq2 = 0.f, xq3 = 0.f;
        if (tid < 128) {
            const float* xp_t = xp_gt + (size_t)t * G4_;
            xq0 = __ldcs(xp_t);
            xq1 = __ldcs(xp_t + 512);
            xq2 = __ldcs(xp_t + 1024);
            xq3 = __ldcs(xp_t + 1536);
        }

#pragma unroll
        for (int i = 0; i < 4; ++i) {
            int idx4 = tid + i * 256;
            int b  = idx4 >> 7;
            int k4 = idx4 & 127;
            *(float4*)&h_s[b * HST + k4 * 4] = hreg[i];
        }
        __syncthreads();

        // ---- dots: 2 z-cols x 8 batches x 64 k, weights from regs ----
        ull acc[2][8];
#pragma unroll
        for (int j = 0; j < 2; ++j)
#pragma unroll
            for (int bi = 0; bi < 8; ++bi) acc[j][bi] = 0ull;

#pragma unroll 4
        for (int kk = 0; kk < 64; kk += 4) {
            ull w0a = wreg[0][kk >> 1], w0b = wreg[0][(kk >> 1) + 1];
            ull w1a = wreg[1][kk >> 1], w1b = wreg[1][(kk >> 1) + 1];
#pragma unroll
            for (int bi = 0; bi < 8; ++bi) {
                float4 hv = *(const float4*)&h_s[bi * HST + k0 + kk];  // bcast
                ull h01 = ((const ull*)&hv)[0], h23 = ((const ull*)&hv)[1];
                acc[0][bi] = fma2(h01, w0a, acc[0][bi]);
                acc[0][bi] = fma2(h23, w0b, acc[0][bi]);
                acc[1][bi] = fma2(h01, w1a, acc[1][bi]);
                acc[1][bi] = fma2(h23, w1b, acc[1][bi]);
            }
        }

        // ---- hadd over k-parity, stash partials ----
#pragma unroll
        for (int bi = 0; bi < 8; ++bi) {
            float2 pr;
            float2 a0 = *(float2*)&acc[0][bi];
            float2 a1 = *(float2*)&acc[1][bi];
            pr.x = a0.x + a0.y;
            pr.y = a1.x + a1.y;
            *(float2*)&part[(ko * 8 + bi) * PST + zct] = pr;
        }
        __syncthreads();

        // ---- merged reduce + gates: 128 threads = 8 b x 16 cols ----
        if (tid < 128) {
            float zi = bsg0 + xq0;
            float zf = bsg1 + xq1;
            float zg = bsg2 + xq2;
            float zo = bsg3 + xq3;
#pragma unroll
            for (int o = 0; o < 8; ++o) {
                const float* pb = &part[(o * 8 + gtb) * PST + gtj];
                zi += pb[0];
                zf += pb[16];
                zg += pb[32];
                zo += pb[48];
            }
            float cn = sigf(zf) * c_s[gtb * 16 + gtj] + sigf(zi) * tanhf_fast(zg);
            float hn = sigf(zo) * tanhf_fast(cn);
            c_s[gtb * 16 + gtj] = cn;
            g_h[par ^ 1][(gb0 + gtb) * H_ + col0 + gtj] = hn;
            __stcs(&out[((size_t)(gb0 + gtb) * T_ + t) * H_ + col0 + gtj], hn);
        }
        __syncthreads();

        // ---- per-bgrp barrier: red + poll (32 arrivals) ----
        if (tid == 0) {
            red_add_release(ctr, 1u);
            unsigned int tgt = (unsigned int)(t + 1) * 32u;
            while (ld_acquire(ctr) < tgt) { }
        }
        __syncthreads();
        par ^= 1;
    }
}

// =====================================================================
// launch
// =====================================================================
extern "C" void kernel_launch(void* const* d_in, const int* in_sizes, int n_in,
                              void* d_out, int out_size) {
    const float* inputs = (const float*)d_in[0];
    // d_in[1] = input_paddings (unused: all tokens valid)
    const float* c0   = (const float*)d_in[2];
    const float* h0   = (const float*)d_in[3];
    const float* Wi   = (const float*)d_in[4];
    const float* Wh   = (const float*)d_in[5];
    const float* bias = (const float*)d_in[6];
    float* out = (float*)d_out;

    dim3 g1(G4_ / BN, (B_ * T_) / BM);   // 16 x 512
    gemm_xproj<<<g1, 256>>>(inputs, Wi);
    init_kernel<<<64, 256>>>(h0);
    lstm_seq<<<128, 256>>>(c0, bias, Wh, out);
}

// round 11
// speedup vs baseline: 1.4555x; 1.4555x over previous
#include <cuda_runtime.h>
#include <math.h>

#define B_  32
#define T_  2048
#define D_  512
#define H_  512
#define G4_ 2048   // 4*H

// ---------------- device scratch ----------------
__device__ float g_xp[(size_t)B_ * T_ * G4_];   // x_proj scratch [B][T][4H]
__device__ float g_h[2][B_ * H_];               // double-buffered hidden state
__device__ unsigned int g_ctr4[4 * 64];         // per-bgrp counters, 256B apart

typedef unsigned long long ull;

// ---------------- packed f32x2 helpers ----------------
__device__ __forceinline__ ull pk(float lo, float hi) {
    ull r;
    asm("mov.b64 %0, {%1, %2};" : "=l"(r) : "f"(lo), "f"(hi));
    return r;
}
__device__ __forceinline__ ull fma2(ull a, ull b, ull c) {
    ull d;
    asm("fma.rn.f32x2 %0, %1, %2, %3;" : "=l"(d) : "l"(a), "l"(b), "l"(c));
    return d;
}

// ---------------- barrier primitives ----------------
__device__ __forceinline__ void red_add_release(unsigned int* p, unsigned int v) {
    asm volatile("red.release.gpu.add.u32 [%0], %1;" :: "l"(p), "r"(v) : "memory");
}
__device__ __forceinline__ unsigned int ld_acquire(unsigned int* p) {
    unsigned int v;
    asm volatile("ld.acquire.gpu.u32 %0, [%1];" : "=r"(v) : "l"(p) : "memory");
    return v;
}

// ---------------- cp.async helpers ----------------
__device__ __forceinline__ void cp4(unsigned int dst, const void* src) {
    asm volatile("cp.async.ca.shared.global [%0], [%1], 4;" :: "r"(dst), "l"(src));
}
__device__ __forceinline__ void cp16(unsigned int dst, const void* src) {
    asm volatile("cp.async.ca.shared.global [%0], [%1], 16;" :: "r"(dst), "l"(src));
}
__device__ __forceinline__ void cp_commit() {
    asm volatile("cp.async.commit_group;");
}
__device__ __forceinline__ void cp_wait0() {
    asm volatile("cp.async.wait_group 0;" ::: "memory");
}

// =====================================================================
// Phase 1: x_proj = inputs @ Wi — cp.async double-buffered,
// v6 compute micro-kernel unchanged, no staging registers.
// =====================================================================
#define BM 128
#define BN 128
#define BKK 8

__global__ __launch_bounds__(256) void gemm_xproj(const float* __restrict__ A,
                                                  const float* __restrict__ Bw) {
    __shared__ __align__(16) float As[2][BKK][BM + 4];
    __shared__ __align__(16) float Bs[2][BKK][BN + 4];

    const int tid = threadIdx.x;
    const int m0 = blockIdx.y * BM;
    const int n0 = blockIdx.x * BN;
    const int tx = tid & 15;
    const int ty = tid >> 4;

    const int arow = tid >> 1;
    const int akq  = (tid & 1) * 4;
    const int bkr  = tid >> 5;
    const int bq   = tid & 31;

    const unsigned int as_base = (unsigned int)__cvta_generic_to_shared(&As[0][0][0]);
    const unsigned int bs_base = (unsigned int)__cvta_generic_to_shared(&Bs[0][0][0]);

    ull acc[8][4];
#pragma unroll
    for (int i = 0; i < 8; i++)
#pragma unroll
        for (int j = 0; j < 4; j++) acc[i][j] = 0ull;

    // issue tile kt into buffer buf
    auto issue = [&](int kt, int buf) {
        const float* asrc = &A[(size_t)(m0 + arow) * D_ + kt * BKK + akq];
#pragma unroll
        for (int i = 0; i < 4; ++i) {
            unsigned int dst = as_base +
                (((buf * BKK) + akq + i) * (BM + 4) + arow) * 4u;
            cp4(dst, asrc + i);
        }
        unsigned int bdst = bs_base +
            (((buf * BKK) + bkr) * (BN + 4) + bq * 4) * 4u;
        cp16(bdst, &Bw[(size_t)(kt * BKK + bkr) * G4_ + n0 + bq * 4]);
        cp_commit();
    };

    issue(0, 0);

    for (int kt = 0; kt < D_ / BKK; ++kt) {
        cp_wait0();
        __syncthreads();           // all copies visible; all readers of next buf done
        if (kt + 1 < D_ / BKK) issue(kt + 1, (kt + 1) & 1);

        const int p = kt & 1;
#pragma unroll
        for (int k = 0; k < BKK; ++k) {
            float4 a0 = *(const float4*)&As[p][k][ty * 8];
            float4 a1 = *(const float4*)&As[p][k][ty * 8 + 4];
            const ull* bp = (const ull*)&Bs[p][k][tx * 8];
            ull b0 = bp[0], b1 = bp[1], b2 = bp[2], b3 = bp[3];
            float ar[8] = {a0.x, a0.y, a0.z, a0.w, a1.x, a1.y, a1.z, a1.w};
#pragma unroll
            for (int i = 0; i < 8; i++) {
                ull a2 = pk(ar[i], ar[i]);
                acc[i][0] = fma2(a2, b0, acc[i][0]);
                acc[i][1] = fma2(a2, b1, acc[i][1]);
                acc[i][2] = fma2(a2, b2, acc[i][2]);
                acc[i][3] = fma2(a2, b3, acc[i][3]);
            }
        }
    }

#pragma unroll
    for (int i = 0; i < 8; i++) {
        size_t row = (size_t)(m0 + ty * 8 + i);
#pragma unroll
        for (int j = 0; j < 4; j++) {
            *(float2*)&g_xp[row * G4_ + n0 + tx * 8 + 2 * j] = *(float2*)&acc[i][j];
        }
    }
}

// =====================================================================
// Init
// =====================================================================
__global__ void init_kernel(const float* __restrict__ h0) {
    int i = blockIdx.x * blockDim.x + threadIdx.x;
    if (i < 4 * 64) g_ctr4[i] = 0u;
    if (i < B_ * H_) g_h[0][i] = h0[i];
}

// =====================================================================
// Phase 2 (v10): v6 skeleton + xp seeded into partials + merged
// reduce/gates + per-bgrp red-barrier. PST=80 -> conflict-free reduce.
// 128 blocks = 4 bgrp x 32 cg; block: 8 batches x 16 h-cols.
// 256 threads = 8 k-octants x 32 zc-pairs; thread: 2 z-cols x 64 k in regs.
// =====================================================================
#define HST 516
#define PST 80

__device__ __forceinline__ float sigf(float x) {
    return __fdividef(1.0f, 1.0f + __expf(-x));
}
__device__ __forceinline__ float tanhf_fast(float x) {
    return __fdividef(2.0f, 1.0f + __expf(-2.0f * x)) - 1.0f;
}

__global__ __launch_bounds__(256, 1) void lstm_seq(const float* __restrict__ c0,
                                                   const float* __restrict__ bias,
                                                   const float* __restrict__ Wh,
                                                   float* __restrict__ out) {
    __shared__ __align__(16) float h_s[8 * HST];     // 16.5 KB
    __shared__ __align__(16) float part[64 * PST];   // 20 KB [oct*8+b][zc]
    __shared__ float c_s[8 * 16];
    __shared__ float b_s[64];

    const int tid = threadIdx.x;
    const int bl  = blockIdx.x;

    const int cg   = bl & 31;
    const int bgrp = bl >> 5;
    const int col0 = cg * 16;
    const int gb0  = bgrp * 8;

    unsigned int* ctr = &g_ctr4[bgrp * 64];   // 256B apart

    // ---- compute mapping: tid = ko*32 + zcp ----
    const int zcp = tid & 31;
    const int ko  = tid >> 5;        // k-octant AND the batch this thread seeds xp for
    const int k0  = ko * 64;
    const int zct = 2 * zcp;

    // ---- gate mapping (tid < 128) ----
    const int gtb = tid >> 4;        // local batch 0..7
    const int gtj = tid & 15;        // h-col 0..15

    // ---- one-time: Wh slice -> registers (2 cols x 64 k) ----
    ull wreg[2][32];
    {
        const int gcolA = (zct >> 4) * H_ + col0 + (zct & 15);
        const int gcolB = ((zct + 1) >> 4) * H_ + col0 + ((zct + 1) & 15);
#pragma unroll
        for (int kk = 0; kk < 64; kk += 2) {
            wreg[0][kk >> 1] = pk(Wh[(size_t)(k0 + kk) * G4_ + gcolA],
                                  Wh[(size_t)(k0 + kk + 1) * G4_ + gcolA]);
            wreg[1][kk >> 1] = pk(Wh[(size_t)(k0 + kk) * G4_ + gcolB],
                                  Wh[(size_t)(k0 + kk + 1) * G4_ + gcolB]);
        }
    }
    if (tid < 64) b_s[tid] = bias[(tid >> 4) * H_ + col0 + (tid & 15)];
    if (tid < 128) c_s[gtb * 16 + gtj] = c0[(gb0 + gtb) * H_ + col0 + gtj];
    __syncthreads();

    // xp pointer for this compute thread: batch gb0+ko, cols gzc(zct), +1
    const int gzc = (zct >> 4) * H_ + col0 + (zct & 15);
    const float* xp_base = g_xp + (size_t)(gb0 + ko) * T_ * G4_ + gzc;

    // gate-thread bias constants
    float bsg0 = 0.f, bsg1 = 0.f, bsg2 = 0.f, bsg3 = 0.f;
    if (tid < 128) {
        bsg0 = b_s[gtj];
        bsg1 = b_s[16 + gtj];
        bsg2 = b_s[32 + gtj];
        bsg3 = b_s[48 + gtj];
    }

    int par = 0;
    for (int t = 0; t < T_; ++t) {
        // ---- stage h slice: 1024 float4, 4 per thread ----
        const float* hsrc = g_h[par] + gb0 * H_;
        float4 hreg[4];
#pragma unroll
        for (int i = 0; i < 4; ++i)
            hreg[i] = __ldcg((const float4*)hsrc + tid + i * 256);

        // prefetch xp for this step (v6 pattern: 256 threads, float2 each)
        float2 xpv = __ldcs((const float2*)(xp_base + (size_t)t * G4_));

#pragma unroll
        for (int i = 0; i < 4; ++i) {
            int idx4 = tid + i * 256;
            int b  = idx4 >> 7;
            int k4 = idx4 & 127;
            *(float4*)&h_s[b * HST + k4 * 4] = hreg[i];
        }
        __syncthreads();

        // ---- dots: 2 z-cols x 8 batches x 64 k, weights from regs ----
        ull acc[2][8];
#pragma unroll
        for (int j = 0; j < 2; ++j)
#pragma unroll
            for (int bi = 0; bi < 8; ++bi) acc[j][bi] = 0ull;

#pragma unroll 4
        for (int kk = 0; kk < 64; kk += 4) {
            ull w0a = wreg[0][kk >> 1], w0b = wreg[0][(kk >> 1) + 1];
            ull w1a = wreg[1][kk >> 1], w1b = wreg[1][(kk >> 1) + 1];
#pragma unroll
            for (int bi = 0; bi < 8; ++bi) {
                float4 hv = *(const float4*)&h_s[bi * HST + k0 + kk];  // bcast
                ull h01 = ((const ull*)&hv)[0], h23 = ((const ull*)&hv)[1];
                acc[0][bi] = fma2(h01, w0a, acc[0][bi]);
                acc[0][bi] = fma2(h23, w0b, acc[0][bi]);
                acc[1][bi] = fma2(h01, w1a, acc[1][bi]);
                acc[1][bi] = fma2(h23, w1b, acc[1][bi]);
            }
        }

        // ---- hadd over k-parity; seed xp for bi==ko; stash partials ----
#pragma unroll
        for (int bi = 0; bi < 8; ++bi) {
            float2 pr;
            float2 a0 = *(float2*)&acc[0][bi];
            float2 a1 = *(float2*)&acc[1][bi];
            pr.x = a0.x + a0.y;
            pr.y = a1.x + a1.y;
            if (bi == ko) { pr.x += xpv.x; pr.y += xpv.y; }
            *(float2*)&part[(ko * 8 + bi) * PST + zct] = pr;
        }
        __syncthreads();

        // ---- merged reduce + gates: 128 threads = 8 b x 16 cols ----
        if (tid < 128) {
            float zi = bsg0;
            float zf = bsg1;
            float zg = bsg2;
            float zo = bsg3;
#pragma unroll
            for (int o = 0; o < 8; ++o) {
                const float* pb = &part[(o * 8 + gtb) * PST + gtj];
                zi += pb[0];
                zf += pb[16];
                zg += pb[32];
                zo += pb[48];
            }
            float cn = sigf(zf) * c_s[gtb * 16 + gtj] + sigf(zi) * tanhf_fast(zg);
            float hn = sigf(zo) * tanhf_fast(cn);
            c_s[gtb * 16 + gtj] = cn;
            g_h[par ^ 1][(gb0 + gtb) * H_ + col0 + gtj] = hn;
            __stcs(&out[((size_t)(gb0 + gtb) * T_ + t) * H_ + col0 + gtj], hn);
        }
        __syncthreads();

        // ---- per-bgrp barrier: red + poll (32 arrivals) ----
        if (tid == 0) {
            red_add_release(ctr, 1u);
            unsigned int tgt = (unsigned int)(t + 1) * 32u;
            while (ld_acquire(ctr) < tgt) { }
        }
        __syncthreads();
        par ^= 1;
    }
}

// =====================================================================
// launch
// =====================================================================
extern "C" void kernel_launch(void* const* d_in, const int* in_sizes, int n_in,
                              void* d_out, int out_size) {
    const float* inputs = (const float*)d_in[0];
    // d_in[1] = input_paddings (unused: all tokens valid)
    const float* c0   = (const float*)d_in[2];
    const float* h0   = (const float*)d_in[3];
    const float* Wi   = (const float*)d_in[4];
    const float* Wh   = (const float*)d_in[5];
    const float* bias = (const float*)d_in[6];
    float* out = (float*)d_out;

    dim3 g1(G4_ / BN, (B_ * T_) / BM);   // 16 x 512
    gemm_xproj<<<g1, 256>>>(inputs, Wi);
    init_kernel<<<64, 256>>>(h0);
    lstm_seq<<<128, 256>>>(c0, bias, Wh, out);
}

// round 12
// speedup vs baseline: 1.4849x; 1.0202x over previous
#include <cuda_runtime.h>
#include <math.h>

#define B_  32
#define T_  2048
#define D_  512
#define H_  512
#define G4_ 2048   // 4*H

// ---------------- device scratch ----------------
__device__ float g_xp[(size_t)B_ * T_ * G4_];   // x_proj scratch [B][T][4H]
__device__ float g_h[2][B_ * H_];               // double-buffered hidden state
__device__ unsigned int g_ctr4[4 * 64];         // per-bgrp counters, 256B apart

typedef unsigned long long ull;

// ---------------- packed f32x2 helpers ----------------
__device__ __forceinline__ ull pk(float lo, float hi) {
    ull r;
    asm("mov.b64 %0, {%1, %2};" : "=l"(r) : "f"(lo), "f"(hi));
    return r;
}
__device__ __forceinline__ ull fma2(ull a, ull b, ull c) {
    ull d;
    asm("fma.rn.f32x2 %0, %1, %2, %3;" : "=l"(d) : "l"(a), "l"(b), "l"(c));
    return d;
}

// ---------------- barrier primitives ----------------
__device__ __forceinline__ void red_add_release(unsigned int* p, unsigned int v) {
    asm volatile("red.release.gpu.add.u32 [%0], %1;" :: "l"(p), "r"(v) : "memory");
}
__device__ __forceinline__ unsigned int ld_acquire(unsigned int* p) {
    unsigned int v;
    asm volatile("ld.acquire.gpu.u32 %0, [%1];" : "=r"(v) : "l"(p) : "memory");
    return v;
}

// =====================================================================
// Phase 1: x_proj = inputs @ Wi  (exact v6 kernel — best measured)
// =====================================================================
#define BM 128
#define BN 128
#define BKK 8

__global__ __launch_bounds__(256) void gemm_xproj(const float* __restrict__ A,
                                                  const float* __restrict__ Bw) {
    __shared__ float As[BKK][BM + 4];
    __shared__ float Bs[BKK][BN + 4];

    const int tid = threadIdx.x;
    const int m0 = blockIdx.y * BM;
    const int n0 = blockIdx.x * BN;
    const int tx = tid & 15;
    const int ty = tid >> 4;

    const int arow = tid >> 1;
    const int akq  = (tid & 1) * 4;
    const int bkr  = tid >> 5;
    const int bq   = tid & 31;

    ull acc[8][4];
#pragma unroll
    for (int i = 0; i < 8; i++)
#pragma unroll
        for (int j = 0; j < 4; j++) acc[i][j] = 0ull;

    for (int kt = 0; kt < D_ / BKK; ++kt) {
        float4 av = *(const float4*)&A[(size_t)(m0 + arow) * D_ + kt * BKK + akq];
        As[akq + 0][arow] = av.x;
        As[akq + 1][arow] = av.y;
        As[akq + 2][arow] = av.z;
        As[akq + 3][arow] = av.w;
        float4 bv = *(const float4*)&Bw[(size_t)(kt * BKK + bkr) * G4_ + n0 + bq * 4];
        *(float4*)&Bs[bkr][bq * 4] = bv;
        __syncthreads();

#pragma unroll
        for (int k = 0; k < BKK; ++k) {
            float4 a0 = *(const float4*)&As[k][ty * 8];
            float4 a1 = *(const float4*)&As[k][ty * 8 + 4];
            const ull* bp = (const ull*)&Bs[k][tx * 8];
            ull b0 = bp[0], b1 = bp[1], b2 = bp[2], b3 = bp[3];
            float ar[8] = {a0.x, a0.y, a0.z, a0.w, a1.x, a1.y, a1.z, a1.w};
#pragma unroll
            for (int i = 0; i < 8; i++) {
                ull a2 = pk(ar[i], ar[i]);
                acc[i][0] = fma2(a2, b0, acc[i][0]);
                acc[i][1] = fma2(a2, b1, acc[i][1]);
                acc[i][2] = fma2(a2, b2, acc[i][2]);
                acc[i][3] = fma2(a2, b3, acc[i][3]);
            }
        }
        __syncthreads();
    }

#pragma unroll
    for (int i = 0; i < 8; i++) {
        size_t row = (size_t)(m0 + ty * 8 + i);
#pragma unroll
        for (int j = 0; j < 4; j++) {
            *(float2*)&g_xp[row * G4_ + n0 + tx * 8 + 2 * j] = *(float2*)&acc[i][j];
        }
    }
}

// =====================================================================
// Init
// =====================================================================
__global__ void init_kernel(const float* __restrict__ h0) {
    int i = blockIdx.x * blockDim.x + threadIdx.x;
    if (i < 4 * 64) g_ctr4[i] = 0u;
    if (i < B_ * H_) g_h[0][i] = h0[i];
}

// =====================================================================
// Phase 2 (v11): 512 threads — 4 warps/SMSP for latency hiding.
// 128 blocks = 4 bgrp x 32 cg; block: 8 batches x 16 h-cols (64 z-cols).
// 512 threads = 16 k-sixteenths (32 k) x 32 zc-pairs.
// Thread: 2 z-cols x 32 k of Wh in regs (32 ull), all 8 batches.
// Per-warp: 256 fma2 vs 64 LDS (4:1). xp via smem buffer.
// =====================================================================
#define HST 516
#define PST 80
#define XST 80

__device__ __forceinline__ float sigf(float x) {
    return __fdividef(1.0f, 1.0f + __expf(-x));
}
__device__ __forceinline__ float tanhf_fast(float x) {
    return __fdividef(2.0f, 1.0f + __expf(-2.0f * x)) - 1.0f;
}

extern __shared__ float smem_dyn[];

__global__ __launch_bounds__(512, 1) void lstm_seq(const float* __restrict__ c0,
                                                   const float* __restrict__ bias,
                                                   const float* __restrict__ Wh,
                                                   float* __restrict__ out) {
    float* h_s  = smem_dyn;                    // [8][HST]   4128 f
    float* xp_s = h_s + 8 * HST;               // [8][XST]    640 f
    float* part = xp_s + 8 * XST;              // [128][PST] 10240 f
    float* c_s  = part + 128 * PST;            // [8*16]
    float* b_s  = c_s + 128;                   // [64]

    const int tid = threadIdx.x;
    const int bl  = blockIdx.x;

    const int cg   = bl & 31;
    const int bgrp = bl >> 5;
    const int col0 = cg * 16;
    const int gb0  = bgrp * 8;

    unsigned int* ctr = &g_ctr4[bgrp * 64];   // 256B apart

    // ---- compute mapping: tid = ko*32 + zcp ----
    const int zcp = tid & 31;
    const int ko  = tid >> 5;        // k-sixteenth 0..15 (= warp id)
    const int k0  = ko * 32;
    const int zct = 2 * zcp;

    // ---- xp staging mapping: tid = xb*64 + xc ----
    const int xb = tid >> 6;         // local batch 0..7
    const int xc = tid & 63;         // z-col 0..63
    const int gxc = (xc >> 4) * H_ + col0 + (xc & 15);

    // ---- gate mapping (tid < 128) ----
    const int gtb = tid >> 4;        // local batch 0..7
    const int gtj = tid & 15;        // h-col 0..15

    // ---- one-time: Wh slice -> registers (2 cols x 32 k = 32 ull) ----
    ull wreg[2][16];
    {
        const int gcolA = (zct >> 4) * H_ + col0 + (zct & 15);
        const int gcolB = ((zct + 1) >> 4) * H_ + col0 + ((zct + 1) & 15);
#pragma unroll
        for (int kk = 0; kk < 32; kk += 2) {
            wreg[0][kk >> 1] = pk(Wh[(size_t)(k0 + kk) * G4_ + gcolA],
                                  Wh[(size_t)(k0 + kk + 1) * G4_ + gcolA]);
            wreg[1][kk >> 1] = pk(Wh[(size_t)(k0 + kk) * G4_ + gcolB],
                                  Wh[(size_t)(k0 + kk + 1) * G4_ + gcolB]);
        }
    }
    if (tid < 64) b_s[tid] = bias[(tid >> 4) * H_ + col0 + (tid & 15)];
    if (tid < 128) c_s[gtb * 16 + gtj] = c0[(gb0 + gtb) * H_ + col0 + gtj];
    __syncthreads();

    const float* xp_src = g_xp + (size_t)(gb0 + xb) * T_ * G4_ + gxc;

    // gate-thread bias constants
    float bsg0 = 0.f, bsg1 = 0.f, bsg2 = 0.f, bsg3 = 0.f;
    if (tid < 128) {
        bsg0 = b_s[gtj];
        bsg1 = b_s[16 + gtj];
        bsg2 = b_s[32 + gtj];
        bsg3 = b_s[48 + gtj];
    }

    int par = 0;
    for (int t = 0; t < T_; ++t) {
        // ---- stage h slice: 1024 float4, 2 per thread + 1 xp float ----
        const float* hsrc = g_h[par] + gb0 * H_;
        float4 h0 = __ldcg((const float4*)hsrc + tid);
        float4 h1 = __ldcg((const float4*)hsrc + tid + 512);
        float xpv = __ldcs(xp_src + (size_t)t * G4_);
        {
            int i0 = tid,        b0i = i0 >> 7, k40 = i0 & 127;
            int i1 = tid + 512,  b1i = i1 >> 7, k41 = i1 & 127;
            *(float4*)&h_s[b0i * HST + k40 * 4] = h0;
            *(float4*)&h_s[b1i * HST + k41 * 4] = h1;
            xp_s[xb * XST + xc] = xpv;
        }
        __syncthreads();

        // ---- dots: 2 z-cols x 8 batches x 32 k, weights from regs ----
        ull acc[2][8];
#pragma unroll
        for (int j = 0; j < 2; ++j)
#pragma unroll
            for (int bi = 0; bi < 8; ++bi) acc[j][bi] = 0ull;

#pragma unroll
        for (int kk = 0; kk < 32; kk += 4) {
            ull w0a = wreg[0][kk >> 1], w0b = wreg[0][(kk >> 1) + 1];
            ull w1a = wreg[1][kk >> 1], w1b = wreg[1][(kk >> 1) + 1];
#pragma unroll
            for (int bi = 0; bi < 8; ++bi) {
                float4 hv = *(const float4*)&h_s[bi * HST + k0 + kk];  // bcast
                ull h01 = ((const ull*)&hv)[0], h23 = ((const ull*)&hv)[1];
                acc[0][bi] = fma2(h01, w0a, acc[0][bi]);
                acc[0][bi] = fma2(h23, w0b, acc[0][bi]);
                acc[1][bi] = fma2(h01, w1a, acc[1][bi]);
                acc[1][bi] = fma2(h23, w1b, acc[1][bi]);
            }
        }

        // ---- hadd over k-parity, stash partials ----
#pragma unroll
        for (int bi = 0; bi < 8; ++bi) {
            float2 pr;
            float2 a0 = *(float2*)&acc[0][bi];
            float2 a1 = *(float2*)&acc[1][bi];
            pr.x = a0.x + a0.y;
            pr.y = a1.x + a1.y;
            *(float2*)&part[(ko * 8 + bi) * PST + zct] = pr;
        }
        __syncthreads();

        // ---- merged reduce + gates: 128 threads = 8 b x 16 cols ----
        if (tid < 128) {
            float zi = bsg0 + xp_s[gtb * XST + gtj];
            float zf = bsg1 + xp_s[gtb * XST + 16 + gtj];
            float zg = bsg2 + xp_s[gtb * XST + 32 + gtj];
            float zo = bsg3 + xp_s[gtb * XST + 48 + gtj];
#pragma unroll
            for (int o = 0; o < 16; ++o) {
                const float* pb = &part[(o * 8 + gtb) * PST + gtj];
                zi += pb[0];
                zf += pb[16];
                zg += pb[32];
                zo += pb[48];
            }
            float cn = sigf(zf) * c_s[gtb * 16 + gtj] + sigf(zi) * tanhf_fast(zg);
            float hn = sigf(zo) * tanhf_fast(cn);
            c_s[gtb * 16 + gtj] = cn;
            g_h[par ^ 1][(gb0 + gtb) * H_ + col0 + gtj] = hn;
            __stcs(&out[((size_t)(gb0 + gtb) * T_ + t) * H_ + col0 + gtj], hn);
        }
        __syncthreads();

        // ---- per-bgrp barrier: red + poll (32 arrivals) ----
        if (tid == 0) {
            red_add_release(ctr, 1u);
            unsigned int tgt = (unsigned int)(t + 1) * 32u;
            while (ld_acquire(ctr) < tgt) { }
        }
        __syncthreads();
        par ^= 1;
    }
}

// =====================================================================
// launch
// =====================================================================
#define LSTM_SMEM_BYTES ((8 * HST + 8 * XST + 128 * PST + 128 + 64) * 4)

extern "C" void kernel_launch(void* const* d_in, const int* in_sizes, int n_in,
                              void* d_out, int out_size) {
    const float* inputs = (const float*)d_in[0];
    // d_in[1] = input_paddings (unused: all tokens valid)
    const float* c0   = (const float*)d_in[2];
    const float* h0   = (const float*)d_in[3];
    const float* Wi   = (const float*)d_in[4];
    const float* Wh   = (const float*)d_in[5];
    const float* bias = (const float*)d_in[6];
    float* out = (float*)d_out;

    cudaFuncSetAttribute(lstm_seq, cudaFuncAttributeMaxDynamicSharedMemorySize,
                         LSTM_SMEM_BYTES);

    dim3 g1(G4_ / BN, (B_ * T_) / BM);   // 16 x 512
    gemm_xproj<<<g1, 256>>>(inputs, Wi);
    init_kernel<<<64, 256>>>(h0);
    lstm_seq<<<128, 512, LSTM_SMEM_BYTES>>>(c0, bias, Wh, out);
}

// round 15
// speedup vs baseline: 1.6179x; 1.0896x over previous
#include <cuda_runtime.h>
#include <math.h>

#define B_  32
#define T_  2048
#define D_  512
#define H_  512
#define G4_ 2048   // 4*H

// ---------------- device scratch ----------------
__device__ float g_xp[(size_t)B_ * T_ * G4_];   // x_proj scratch [B][T][4H]
__device__ float g_h[2][B_ * H_];               // double-buffered hidden state
__device__ unsigned int g_pcnt[4][32 * 32];     // per-producer counters, 128B apart

typedef unsigned long long ull;

// ---------------- packed f32x2 helpers ----------------
__device__ __forceinline__ ull pk(float lo, float hi) {
    ull r;
    asm("mov.b64 %0, {%1, %2};" : "=l"(r) : "f"(lo), "f"(hi));
    return r;
}
__device__ __forceinline__ ull fma2(ull a, ull b, ull c) {
    ull d;
    asm("fma.rn.f32x2 %0, %1, %2, %3;" : "=l"(d) : "l"(a), "l"(b), "l"(c));
    return d;
}

// ---------------- sync primitives ----------------
__device__ __forceinline__ void red_add_release(unsigned int* p, unsigned int v) {
    asm volatile("red.release.gpu.add.u32 [%0], %1;" :: "l"(p), "r"(v) : "memory");
}
__device__ __forceinline__ unsigned int ld_acquire(unsigned int* p) {
    unsigned int v;
    asm volatile("ld.acquire.gpu.u32 %0, [%1];" : "=r"(v) : "l"(p) : "memory");
    return v;
}

// =====================================================================
// Phase 1: x_proj = inputs @ Wi  (exact v6 kernel — best measured)
// =====================================================================
#define BM 128
#define BN 128
#define BKK 8

__global__ __launch_bounds__(256) void gemm_xproj(const float* __restrict__ A,
                                                  const float* __restrict__ Bw) {
    __shared__ float As[BKK][BM + 4];
    __shared__ float Bs[BKK][BN + 4];

    const int tid = threadIdx.x;
    const int m0 = blockIdx.y * BM;
    const int n0 = blockIdx.x * BN;
    const int tx = tid & 15;
    const int ty = tid >> 4;

    const int arow = tid >> 1;
    const int akq  = (tid & 1) * 4;
    const int bkr  = tid >> 5;
    const int bq   = tid & 31;

    ull acc[8][4];
#pragma unroll
    for (int i = 0; i < 8; i++)
#pragma unroll
        for (int j = 0; j < 4; j++) acc[i][j] = 0ull;

    for (int kt = 0; kt < D_ / BKK; ++kt) {
        float4 av = *(const float4*)&A[(size_t)(m0 + arow) * D_ + kt * BKK + akq];
        As[akq + 0][arow] = av.x;
        As[akq + 1][arow] = av.y;
        As[akq + 2][arow] = av.z;
        As[akq + 3][arow] = av.w;
        float4 bv = *(const float4*)&Bw[(size_t)(kt * BKK + bkr) * G4_ + n0 + bq * 4];
        *(float4*)&Bs[bkr][bq * 4] = bv;
        __syncthreads();

#pragma unroll
        for (int k = 0; k < BKK; ++k) {
            float4 a0 = *(const float4*)&As[k][ty * 8];
            float4 a1 = *(const float4*)&As[k][ty * 8 + 4];
            const ull* bp = (const ull*)&Bs[k][tx * 8];
            ull b0 = bp[0], b1 = bp[1], b2 = bp[2], b3 = bp[3];
            float ar[8] = {a0.x, a0.y, a0.z, a0.w, a1.x, a1.y, a1.z, a1.w};
#pragma unroll
            for (int i = 0; i < 8; i++) {
                ull a2 = pk(ar[i], ar[i]);
                acc[i][0] = fma2(a2, b0, acc[i][0]);
                acc[i][1] = fma2(a2, b1, acc[i][1]);
                acc[i][2] = fma2(a2, b2, acc[i][2]);
                acc[i][3] = fma2(a2, b3, acc[i][3]);
            }
        }
        __syncthreads();
    }

#pragma unroll
    for (int i = 0; i < 8; i++) {
        size_t row = (size_t)(m0 + ty * 8 + i);
#pragma unroll
        for (int j = 0; j < 4; j++) {
            *(float2*)&g_xp[row * G4_ + n0 + tx * 8 + 2 * j] = *(float2*)&acc[i][j];
        }
    }
}

// =====================================================================
// Init: zero per-producer counters, load h0
// =====================================================================
__global__ void init_kernel(const float* __restrict__ h0) {
    int i = blockIdx.x * blockDim.x + threadIdx.x;
    if (i < 4 * 32 * 32) ((unsigned int*)g_pcnt)[i] = 0u;
    if (i < B_ * H_) g_h[0][i] = h0[i];
}

// =====================================================================
// Phase 2 (v12): chunked producer/consumer h exchange.
// 128 blocks = 4 bgrp x 32 cg; block: 8 batches x 16 h-cols (64 z-cols).
// 512 threads = 16 warps; warp w stages producer chunks 2w, 2w+1 as
// each becomes ready (per-producer counters). Own chunk written to h_s
// directly by gates. No central barrier.
// Compute: thread = (k-sixteenth, zc-pair): 2 z-cols x 32 k in regs.
// =====================================================================
#define HST 516
#define PST 80
#define XST 80

__device__ __forceinline__ float sigf(float x) {
    return __fdividef(1.0f, 1.0f + __expf(-x));
}
__device__ __forceinline__ float tanhf_fast(float x) {
    return __fdividef(2.0f, 1.0f + __expf(-2.0f * x)) - 1.0f;
}

extern __shared__ float smem_dyn[];

__global__ __launch_bounds__(512, 1) void lstm_seq(const float* __restrict__ c0,
                                                   const float* __restrict__ bias,
                                                   const float* __restrict__ Wh,
                                                   float* __restrict__ out) {
    float* h_s  = smem_dyn;                    // [8][HST]
    float* xp_s = h_s + 8 * HST;               // [8][XST]
    float* part = xp_s + 8 * XST;              // [128][PST]
    float* c_s  = part + 128 * PST;            // [8*16]
    float* b_s  = c_s + 128;                   // [64]

    const int tid  = threadIdx.x;
    const int lane = tid & 31;
    const int wrp  = tid >> 5;
    const int bl   = blockIdx.x;

    const int cg   = bl & 31;
    const int bgrp = bl >> 5;
    const int col0 = cg * 16;
    const int gb0  = bgrp * 8;

    unsigned int* cnt_base = &g_pcnt[bgrp][0];      // producer p at +p*32
    unsigned int* my_cnt   = &g_pcnt[bgrp][cg * 32];

    // ---- compute mapping: tid = ko*32 + zcp ----
    const int zcp = tid & 31;
    const int ko  = wrp;             // k-sixteenth 0..15
    const int k0  = ko * 32;
    const int zct = 2 * zcp;

    // ---- staging: warp w handles producers 2w, 2w+1; lane -> (b, c4) ----
    const int sb = lane >> 2;        // local batch 0..7
    const int sc4 = lane & 3;        // float4 index within 16 cols

    // ---- xp staging mapping: tid = xb*64 + xc ----
    const int xb = tid >> 6;
    const int xc = tid & 63;
    const int gxc = (xc >> 4) * H_ + col0 + (xc & 15);

    // ---- gate mapping (tid < 128) ----
    const int gtb = tid >> 4;
    const int gtj = tid & 15;

    // ---- one-time: Wh slice -> registers (2 cols x 32 k = 32 ull) ----
    ull wreg[2][16];
    {
        const int gcolA = (zct >> 4) * H_ + col0 + (zct & 15);
        const int gcolB = ((zct + 1) >> 4) * H_ + col0 + ((zct + 1) & 15);
#pragma unroll
        for (int kk = 0; kk < 32; kk += 2) {
            wreg[0][kk >> 1] = pk(Wh[(size_t)(k0 + kk) * G4_ + gcolA],
                                  Wh[(size_t)(k0 + kk + 1) * G4_ + gcolA]);
            wreg[1][kk >> 1] = pk(Wh[(size_t)(k0 + kk) * G4_ + gcolB],
                                  Wh[(size_t)(k0 + kk + 1) * G4_ + gcolB]);
        }
    }
    if (tid < 64) b_s[tid] = bias[(tid >> 4) * H_ + col0 + (tid & 15)];
    if (tid < 128) c_s[gtb * 16 + gtj] = c0[(gb0 + gtb) * H_ + col0 + gtj];
    __syncthreads();

    const float* xp_src = g_xp + (size_t)(gb0 + xb) * T_ * G4_ + gxc;

    float bsg0 = 0.f, bsg1 = 0.f, bsg2 = 0.f, bsg3 = 0.f;
    if (tid < 128) {
        bsg0 = b_s[gtj];
        bsg1 = b_s[16 + gtj];
        bsg2 = b_s[32 + gtj];
        bsg3 = b_s[48 + gtj];
    }

    int par = 0;
    for (int t = 0; t < T_; ++t) {
        // ---- xp prefetch (independent of h exchange) ----
        float xpv = __ldcs(xp_src + (size_t)t * G4_);

        // ---- chunked h staging: warp w -> producers 2w, 2w+1 ----
        const float* hsrc = g_h[par];
#pragma unroll
        for (int pi = 0; pi < 2; ++pi) {
            const int p = 2 * wrp + pi;
            if (p == cg && t != 0) continue;   // own chunk written by gates
            // poll producer p (lane 0, broadcast)
            unsigned int v;
            do {
                v = (lane == 0) ? ld_acquire(cnt_base + p * 32) : 0u;
                v = __shfl_sync(0xffffffffu, v, 0);
            } while (v < (unsigned int)t);
            float4 hv = __ldcg((const float4*)(hsrc + (size_t)(gb0 + sb) * H_ + p * 16) + sc4);
            *(float4*)&h_s[sb * HST + p * 16 + sc4 * 4] = hv;
        }
        xp_s[xb * XST + xc] = xpv;
        __syncthreads();

        // ---- dots: 2 z-cols x 8 batches x 32 k, weights from regs ----
        ull acc[2][8];
#pragma unroll
        for (int j = 0; j < 2; ++j)
#pragma unroll
            for (int bi = 0; bi < 8; ++bi) acc[j][bi] = 0ull;

#pragma unroll
        for (int kk = 0; kk < 32; kk += 4) {
            ull w0a = wreg[0][kk >> 1], w0b = wreg[0][(kk >> 1) + 1];
            ull w1a = wreg[1][kk >> 1], w1b = wreg[1][(kk >> 1) + 1];
#pragma unroll
            for (int bi = 0; bi < 8; ++bi) {
                float4 hv = *(const float4*)&h_s[bi * HST + k0 + kk];  // bcast
                ull h01 = ((const ull*)&hv)[0], h23 = ((const ull*)&hv)[1];
                acc[0][bi] = fma2(h01, w0a, acc[0][bi]);
                acc[0][bi] = fma2(h23, w0b, acc[0][bi]);
                acc[1][bi] = fma2(h01, w1a, acc[1][bi]);
                acc[1][bi] = fma2(h23, w1b, acc[1][bi]);
            }
        }

        // ---- hadd over k-parity, stash partials ----
#pragma unroll
        for (int bi = 0; bi < 8; ++bi) {
            float2 pr;
            float2 a0 = *(float2*)&acc[0][bi];
            float2 a1 = *(float2*)&acc[1][bi];
            pr.x = a0.x + a0.y;
            pr.y = a1.x + a1.y;
            *(float2*)&part[(ko * 8 + bi) * PST + zct] = pr;
        }
        __syncthreads();

        // ---- merged reduce + gates: 128 threads = 8 b x 16 cols ----
        if (tid < 128) {
            float zi = bsg0 + xp_s[gtb * XST + gtj];
            float zf = bsg1 + xp_s[gtb * XST + 16 + gtj];
            float zg = bsg2 + xp_s[gtb * XST + 32 + gtj];
            float zo = bsg3 + xp_s[gtb * XST + 48 + gtj];
#pragma unroll
            for (int o = 0; o < 16; ++o) {
                const float* pb = &part[(o * 8 + gtb) * PST + gtj];
                zi += pb[0];
                zf += pb[16];
                zg += pb[32];
                zo += pb[48];
            }
            float cn = sigf(zf) * c_s[gtb * 16 + gtj] + sigf(zi) * tanhf_fast(zg);
            float hn = sigf(zo) * tanhf_fast(cn);
            c_s[gtb * 16 + gtj] = cn;
            g_h[par ^ 1][(gb0 + gtb) * H_ + col0 + gtj] = hn;   // for peers
            h_s[gtb * HST + col0 + gtj] = hn;                   // own chunk, next step
            __stcs(&out[((size_t)(gb0 + gtb) * T_ + t) * H_ + col0 + gtj], hn);
        }
        __syncthreads();

        // ---- announce: state(t+1) published ----
        if (tid == 0) red_add_release(my_cnt, 1u);
        par ^= 1;
    }
}

// =====================================================================
// launch
// =====================================================================
#define LSTM_SMEM_BYTES ((8 * HST + 8 * XST + 128 * PST + 128 + 64) * 4)

extern "C" void kernel_launch(void* const* d_in, const int* in_sizes, int n_in,
                              void* d_out, int out_size) {
    const float* inputs = (const float*)d_in[0];
    // d_in[1] = input_paddings (unused: all tokens valid)
    const float* c0   = (const float*)d_in[2];
    const float* h0   = (const float*)d_in[3];
    const float* Wi   = (const float*)d_in[4];
    const float* Wh   = (const float*)d_in[5];
    const float* bias = (const float*)d_in[6];
    float* out = (float*)d_out;

    cudaFuncSetAttribute(lstm_seq, cudaFuncAttributeMaxDynamicSharedMemorySize,
                         LSTM_SMEM_BYTES);

    dim3 g1(G4_ / BN, (B_ * T_) / BM);   // 16 x 512
    gemm_xproj<<<g1, 256>>>(inputs, Wi);
    init_kernel<<<64, 256>>>(h0);
    lstm_seq<<<128, 512, LSTM_SMEM_BYTES>>>(c0, bias, Wh, out);
}

// round 16
// speedup vs baseline: 1.6241x; 1.0038x over previous
#include <cuda_runtime.h>
#include <math.h>

#define B_  32
#define T_  2048
#define D_  512
#define H_  512
#define G4_ 2048   // 4*H

// ---------------- device scratch ----------------
__device__ float g_xp[(size_t)B_ * T_ * G4_];   // x_proj scratch [B][T][4H]
__device__ float g_h[2][B_ * H_];               // double-buffered hidden state
__device__ unsigned int g_pcnt[4][32 * 64];     // per-producer counters, 256B apart

typedef unsigned long long ull;

// ---------------- packed f32x2 helpers ----------------
__device__ __forceinline__ ull pk(float lo, float hi) {
    ull r;
    asm("mov.b64 %0, {%1, %2};" : "=l"(r) : "f"(lo), "f"(hi));
    return r;
}
__device__ __forceinline__ ull fma2(ull a, ull b, ull c) {
    ull d;
    asm("fma.rn.f32x2 %0, %1, %2, %3;" : "=l"(d) : "l"(a), "l"(b), "l"(c));
    return d;
}

// ---------------- sync primitives ----------------
__device__ __forceinline__ void red_add_release(unsigned int* p, unsigned int v) {
    asm volatile("red.release.gpu.add.u32 [%0], %1;" :: "l"(p), "r"(v) : "memory");
}
__device__ __forceinline__ unsigned int ld_acquire(unsigned int* p) {
    unsigned int v;
    asm volatile("ld.acquire.gpu.u32 %0, [%1];" : "=r"(v) : "l"(p) : "memory");
    return v;
}

// =====================================================================
// Phase 1: x_proj = inputs @ Wi  (exact v6 kernel — best measured)
// =====================================================================
#define BM 128
#define BN 128
#define BKK 8

__global__ __launch_bounds__(256) void gemm_xproj(const float* __restrict__ A,
                                                  const float* __restrict__ Bw) {
    __shared__ float As[BKK][BM + 4];
    __shared__ float Bs[BKK][BN + 4];

    const int tid = threadIdx.x;
    const int m0 = blockIdx.y * BM;
    const int n0 = blockIdx.x * BN;
    const int tx = tid & 15;
    const int ty = tid >> 4;

    const int arow = tid >> 1;
    const int akq  = (tid & 1) * 4;
    const int bkr  = tid >> 5;
    const int bq   = tid & 31;

    ull acc[8][4];
#pragma unroll
    for (int i = 0; i < 8; i++)
#pragma unroll
        for (int j = 0; j < 4; j++) acc[i][j] = 0ull;

    for (int kt = 0; kt < D_ / BKK; ++kt) {
        float4 av = *(const float4*)&A[(size_t)(m0 + arow) * D_ + kt * BKK + akq];
        As[akq + 0][arow] = av.x;
        As[akq + 1][arow] = av.y;
        As[akq + 2][arow] = av.z;
        As[akq + 3][arow] = av.w;
        float4 bv = *(const float4*)&Bw[(size_t)(kt * BKK + bkr) * G4_ + n0 + bq * 4];
        *(float4*)&Bs[bkr][bq * 4] = bv;
        __syncthreads();

#pragma unroll
        for (int k = 0; k < BKK; ++k) {
            float4 a0 = *(const float4*)&As[k][ty * 8];
            float4 a1 = *(const float4*)&As[k][ty * 8 + 4];
            const ull* bp = (const ull*)&Bs[k][tx * 8];
            ull b0 = bp[0], b1 = bp[1], b2 = bp[2], b3 = bp[3];
            float ar[8] = {a0.x, a0.y, a0.z, a0.w, a1.x, a1.y, a1.z, a1.w};
#pragma unroll
            for (int i = 0; i < 8; i++) {
                ull a2 = pk(ar[i], ar[i]);
                acc[i][0] = fma2(a2, b0, acc[i][0]);
                acc[i][1] = fma2(a2, b1, acc[i][1]);
                acc[i][2] = fma2(a2, b2, acc[i][2]);
                acc[i][3] = fma2(a2, b3, acc[i][3]);
            }
        }
        __syncthreads();
    }

#pragma unroll
    for (int i = 0; i < 8; i++) {
        size_t row = (size_t)(m0 + ty * 8 + i);
#pragma unroll
        for (int j = 0; j < 4; j++) {
            *(float2*)&g_xp[row * G4_ + n0 + tx * 8 + 2 * j] = *(float2*)&acc[i][j];
        }
    }
}

// =====================================================================
// Init: zero per-producer counters, load h0
// =====================================================================
__global__ void init_kernel(const float* __restrict__ h0) {
    int i = blockIdx.x * blockDim.x + threadIdx.x;
    if (i < 4 * 32 * 64) ((unsigned int*)g_pcnt)[i] = 0u;
    if (i < B_ * H_) g_h[0][i] = h0[i];
}

// =====================================================================
// Phase 2 (v13): per-warp decoupled poll/stage/compute.
// 128 blocks = 4 bgrp x 32 cg; block: 8 batches x 16 h-cols (64 z-cols).
// 512 threads = 16 warps. Warp w: polls ONLY producers 2w, 2w+1,
// stages their chunks, computes k in [32w, 32w+32) immediately
// (warp-private h_s region) — no pre-compute block barrier.
// Straggler producers overlap with other warps' compute.
// =====================================================================
#define HST 516
#define PST 80
#define XST 80

__device__ __forceinline__ float sigf(float x) {
    return __fdividef(1.0f, 1.0f + __expf(-x));
}
__device__ __forceinline__ float tanhf_fast(float x) {
    return __fdividef(2.0f, 1.0f + __expf(-2.0f * x)) - 1.0f;
}

extern __shared__ float smem_dyn[];

__global__ __launch_bounds__(512, 1) void lstm_seq(const float* __restrict__ c0,
                                                   const float* __restrict__ bias,
                                                   const float* __restrict__ Wh,
                                                   float* __restrict__ out) {
    float* h_s  = smem_dyn;                    // [8][HST]
    float* xp_s = h_s + 8 * HST;               // [8][XST]
    float* part = xp_s + 8 * XST;              // [128][PST]
    float* c_s  = part + 128 * PST;            // [8*16]
    float* b_s  = c_s + 128;                   // [64]

    const int tid  = threadIdx.x;
    const int lane = tid & 31;
    const int wrp  = tid >> 5;
    const int bl   = blockIdx.x;

    const int cg   = bl & 31;
    const int bgrp = bl >> 5;
    const int col0 = cg * 16;
    const int gb0  = bgrp * 8;

    unsigned int* cnt_base = &g_pcnt[bgrp][0];      // producer p at +p*64
    unsigned int* my_cnt   = &g_pcnt[bgrp][cg * 64];

    // ---- compute mapping: warp = k-sixteenth, lane = zc-pair ----
    const int zcp = lane;
    const int ko  = wrp;             // 0..15
    const int k0  = ko * 32;
    const int zct = 2 * zcp;

    // ---- staging: warp w handles producers 2w, 2w+1; lane -> (b, c4) ----
    const int sb  = lane >> 2;       // local batch 0..7
    const int sc4 = lane & 3;        // float4 within 16 cols

    // ---- xp staging mapping: tid = xb*64 + xc ----
    const int xb = tid >> 6;
    const int xc = tid & 63;
    const int gxc = (xc >> 4) * H_ + col0 + (xc & 15);

    // ---- gate mapping (tid < 128) ----
    const int gtb = tid >> 4;
    const int gtj = tid & 15;

    // ---- one-time: Wh slice -> registers (2 cols x 32 k = 32 ull) ----
    ull wreg[2][16];
    {
        const int gcolA = (zct >> 4) * H_ + col0 + (zct & 15);
        const int gcolB = ((zct + 1) >> 4) * H_ + col0 + ((zct + 1) & 15);
#pragma unroll
        for (int kk = 0; kk < 32; kk += 2) {
            wreg[0][kk >> 1] = pk(Wh[(size_t)(k0 + kk) * G4_ + gcolA],
                                  Wh[(size_t)(k0 + kk + 1) * G4_ + gcolA]);
            wreg[1][kk >> 1] = pk(Wh[(size_t)(k0 + kk) * G4_ + gcolB],
                                  Wh[(size_t)(k0 + kk + 1) * G4_ + gcolB]);
        }
    }
    if (tid < 64) b_s[tid] = bias[(tid >> 4) * H_ + col0 + (tid & 15)];
    if (tid < 128) c_s[gtb * 16 + gtj] = c0[(gb0 + gtb) * H_ + col0 + gtj];
    __syncthreads();

    const float* xp_src = g_xp + (size_t)(gb0 + xb) * T_ * G4_ + gxc;

    float bsg0 = 0.f, bsg1 = 0.f, bsg2 = 0.f, bsg3 = 0.f;
    if (tid < 128) {
        bsg0 = b_s[gtj];
        bsg1 = b_s[16 + gtj];
        bsg2 = b_s[32 + gtj];
        bsg3 = b_s[48 + gtj];
    }

    int par = 0;
    for (int t = 0; t < T_; ++t) {
        // ---- xp prefetch ----
        float xpv = __ldcs(xp_src + (size_t)t * G4_);

        // ---- per-warp: poll + stage own 2 chunks, no block barrier ----
        const float* hsrc = g_h[par];
#pragma unroll
        for (int pi = 0; pi < 2; ++pi) {
            const int p = 2 * wrp + pi;
            if (p == cg && t != 0) continue;   // own chunk written by gates
            unsigned int v;
            do {
                v = (lane == 0) ? ld_acquire(cnt_base + p * 64) : 0u;
                v = __shfl_sync(0xffffffffu, v, 0);
            } while (v < (unsigned int)t);
            float4 hv = __ldcg((const float4*)(hsrc + (size_t)(gb0 + sb) * H_ + p * 16) + sc4);
            *(float4*)&h_s[sb * HST + p * 16 + sc4 * 4] = hv;
        }
        xp_s[xb * XST + xc] = xpv;
        __syncwarp();                           // warp-private region ready

        // ---- dots: 2 z-cols x 8 batches x 32 k, weights from regs ----
        ull acc[2][8];
#pragma unroll
        for (int j = 0; j < 2; ++j)
#pragma unroll
            for (int bi = 0; bi < 8; ++bi) acc[j][bi] = 0ull;

#pragma unroll
        for (int kk = 0; kk < 32; kk += 4) {
            ull w0a = wreg[0][kk >> 1], w0b = wreg[0][(kk >> 1) + 1];
            ull w1a = wreg[1][kk >> 1], w1b = wreg[1][(kk >> 1) + 1];
#pragma unroll
            for (int bi = 0; bi < 8; ++bi) {
                float4 hv = *(const float4*)&h_s[bi * HST + k0 + kk];  // bcast
                ull h01 = ((const ull*)&hv)[0], h23 = ((const ull*)&hv)[1];
                acc[0][bi] = fma2(h01, w0a, acc[0][bi]);
                acc[0][bi] = fma2(h23, w0b, acc[0][bi]);
                acc[1][bi] = fma2(h01, w1a, acc[1][bi]);
                acc[1][bi] = fma2(h23, w1b, acc[1][bi]);
            }
        }

        // ---- hadd over k-parity, stash partials ----
#pragma unroll
        for (int bi = 0; bi < 8; ++bi) {
            float2 pr;
            float2 a0 = *(float2*)&acc[0][bi];
            float2 a1 = *(float2*)&acc[1][bi];
            pr.x = a0.x + a0.y;
            pr.y = a1.x + a1.y;
            *(float2*)&part[(ko * 8 + bi) * PST + zct] = pr;
        }
        __syncthreads();                        // all partials + xp_s visible

        // ---- merged reduce + gates: 128 threads = 8 b x 16 cols ----
        if (tid < 128) {
            float zi = bsg0 + xp_s[gtb * XST + gtj];
            float zf = bsg1 + xp_s[gtb * XST + 16 + gtj];
            float zg = bsg2 + xp_s[gtb * XST + 32 + gtj];
            float zo = bsg3 + xp_s[gtb * XST + 48 + gtj];
#pragma unroll
            for (int o = 0; o < 16; ++o) {
                const float* pb = &part[(o * 8 + gtb) * PST + gtj];
                zi += pb[0];
                zf += pb[16];
                zg += pb[32];
                zo += pb[48];
            }
            float cn = sigf(zf) * c_s[gtb * 16 + gtj] + sigf(zi) * tanhf_fast(zg);
            float hn = sigf(zo) * tanhf_fast(cn);
            c_s[gtb * 16 + gtj] = cn;
            g_h[par ^ 1][(gb0 + gtb) * H_ + col0 + gtj] = hn;   // for peers
            h_s[gtb * HST + col0 + gtj] = hn;                   // own chunk, next step
            __stcs(&out[((size_t)(gb0 + gtb) * T_ + t) * H_ + col0 + gtj], hn);

            // early publish: gate warps only, then one release
            asm volatile("bar.sync 1, 128;" ::: "memory");
            if (tid == 0) red_add_release(my_cnt, 1u);
        }
        __syncthreads();                        // fences gate reads vs t+1 writes
        par ^= 1;
    }
}

// =====================================================================
// launch
// =====================================================================
#define LSTM_SMEM_BYTES ((8 * HST + 8 * XST + 128 * PST + 128 + 64) * 4)

extern "C" void kernel_launch(void* const* d_in, const int* in_sizes, int n_in,
                              void* d_out, int out_size) {
    const float* inputs = (const float*)d_in[0];
    // d_in[1] = input_paddings (unused: all tokens valid)
    const float* c0   = (const float*)d_in[2];
    const float* h0   = (const float*)d_in[3];
    const float* Wi   = (const float*)d_in[4];
    const float* Wh   = (const float*)d_in[5];
    const float* bias = (const float*)d_in[6];
    float* out = (float*)d_out;

    cudaFuncSetAttribute(lstm_seq, cudaFuncAttributeMaxDynamicSharedMemorySize,
                         LSTM_SMEM_BYTES);

    dim3 g1(G4_ / BN, (B_ * T_) / BM);   // 16 x 512
    gemm_xproj<<<g1, 256>>>(inputs, Wi);
    init_kernel<<<64, 256>>>(h0);
    lstm_seq<<<128, 512, LSTM_SMEM_BYTES>>>(c0, bias, Wh, out);
}